// round 1
// baseline (speedup 1.0000x reference)
#include <cuda_runtime.h>
#include <math.h>

#define BB 4
#define SEQ 1024
#define HIDDEN 4096
#define NH 32
#define NKV 8
#define DH 128
#define RL 16
#define QDIM (NH*DH)     // 4096
#define KVDIM (NKV*DH)   // 1024

// ---------------- scratch (device globals; no allocations allowed) ----------
__device__ float g_q[(size_t)BB*SEQ*QDIM];
__device__ float g_k[(size_t)BB*SEQ*KVDIM];
__device__ float g_v[(size_t)BB*SEQ*KVDIM];
__device__ float g_attn[(size_t)BB*SEQ*QDIM];
__device__ float g_t[(size_t)BB*SEQ*RL];
__device__ float g_cos[SEQ*(DH/2)];
__device__ float g_sin[SEQ*(DH/2)];

// ---------------- RoPE tables ----------------------------------------------
__global__ void rope_tables_kernel() {
    int idx = blockIdx.x * blockDim.x + threadIdx.x;
    if (idx >= SEQ * (DH/2)) return;
    int s = idx / (DH/2);
    int j = idx % (DH/2);
    // inv_freq = theta^(-(2j)/DH) = 2^(-j * log2(10000)/64)
    float e = -(float)j * (13.287712379549449f / 64.0f);
    float inv = exp2f(e);
    float ang = (float)s * inv;
    g_cos[idx] = cosf(ang);
    g_sin[idx] = sinf(ang);
}

// ---------------- LoRA A-side: t[b,s,r] = sum_i x[b,s,i] * A[b,r,i] ---------
__global__ __launch_bounds__(128) void lora_a_kernel(
    const float* __restrict__ x, const float* __restrict__ A,
    float* __restrict__ t, int K)
{
    int row = blockIdx.x;            // b*SEQ + s
    int b = row / SEQ;
    const float* xr = x + (size_t)row * K;
    const float* Ab = A + (size_t)b * RL * K;

    float acc[RL];
#pragma unroll
    for (int r = 0; r < RL; r++) acc[r] = 0.f;

    for (int i = threadIdx.x; i < K; i += 128) {
        float xv = xr[i];
#pragma unroll
        for (int r = 0; r < RL; r++) acc[r] = fmaf(xv, Ab[(size_t)r*K + i], acc[r]);
    }

    __shared__ float red[RL][128];
#pragma unroll
    for (int r = 0; r < RL; r++) red[r][threadIdx.x] = acc[r];
    __syncthreads();
    for (int s = 64; s > 0; s >>= 1) {
        if (threadIdx.x < s) {
#pragma unroll
            for (int r = 0; r < RL; r++) red[r][threadIdx.x] += red[r][threadIdx.x + s];
        }
        __syncthreads();
    }
    if (threadIdx.x < RL) t[(size_t)row * RL + threadIdx.x] = red[threadIdx.x][0];
}

// ---------------- GEMM + LoRA-B epilogue ------------------------------------
// C[b] (SEQ x N) = X[b] (SEQ x K) @ W^T (W is [N,K]) + T[b] (SEQ x 16) @ BL[b]^T (BL is [B,N,16])
__global__ __launch_bounds__(256) void gemm_lora_kernel(
    const float* __restrict__ X, const float* __restrict__ W,
    const float* __restrict__ T, const float* __restrict__ BL,
    float* __restrict__ C, int N, int K)
{
    __shared__ float As[16][128];
    __shared__ float Bs[16][128];
    __shared__ float Ts[128][16];
    __shared__ float Us[128][16];

    const int b  = blockIdx.z;
    const int n0 = blockIdx.x * 128;
    const int m0 = blockIdx.y * 128;
    const float* Xb = X + (size_t)b * SEQ * K;
    const float* Tb = T + (size_t)b * SEQ * RL;
    const float* Ub = BL + (size_t)b * N * RL;
    float* Cb = C + (size_t)b * SEQ * N;

    const int tid = threadIdx.x;
    const int tx = tid & 15;
    const int ty = tid >> 4;
    const int lr = tid >> 2;          // 0..63
    const int lc = (tid & 3) << 2;    // 0,4,8,12

    float acc[8][8];
#pragma unroll
    for (int i = 0; i < 8; i++)
#pragma unroll
        for (int j = 0; j < 8; j++) acc[i][j] = 0.f;

    const float* xA0 = Xb + (size_t)(m0 + lr)      * K + lc;
    const float* xA1 = Xb + (size_t)(m0 + lr + 64) * K + lc;
    const float* wB0 = W  + (size_t)(n0 + lr)      * K + lc;
    const float* wB1 = W  + (size_t)(n0 + lr + 64) * K + lc;

    for (int k0 = 0; k0 < K; k0 += 16) {
        float4 a0 = *(const float4*)(xA0 + k0);
        float4 a1 = *(const float4*)(xA1 + k0);
        float4 b0 = *(const float4*)(wB0 + k0);
        float4 b1 = *(const float4*)(wB1 + k0);
        __syncthreads();
        As[lc+0][lr] = a0.x; As[lc+1][lr] = a0.y; As[lc+2][lr] = a0.z; As[lc+3][lr] = a0.w;
        As[lc+0][lr+64] = a1.x; As[lc+1][lr+64] = a1.y; As[lc+2][lr+64] = a1.z; As[lc+3][lr+64] = a1.w;
        Bs[lc+0][lr] = b0.x; Bs[lc+1][lr] = b0.y; Bs[lc+2][lr] = b0.z; Bs[lc+3][lr] = b0.w;
        Bs[lc+0][lr+64] = b1.x; Bs[lc+1][lr+64] = b1.y; Bs[lc+2][lr+64] = b1.z; Bs[lc+3][lr+64] = b1.w;
        __syncthreads();
#pragma unroll
        for (int kk = 0; kk < 16; kk++) {
            float4 ra0 = *(const float4*)&As[kk][ty*4];
            float4 ra1 = *(const float4*)&As[kk][ty*4 + 64];
            float4 rb0 = *(const float4*)&Bs[kk][tx*4];
            float4 rb1 = *(const float4*)&Bs[kk][tx*4 + 64];
            float a[8] = {ra0.x, ra0.y, ra0.z, ra0.w, ra1.x, ra1.y, ra1.z, ra1.w};
            float bb[8] = {rb0.x, rb0.y, rb0.z, rb0.w, rb1.x, rb1.y, rb1.z, rb1.w};
#pragma unroll
            for (int i = 0; i < 8; i++)
#pragma unroll
                for (int j = 0; j < 8; j++)
                    acc[i][j] = fmaf(a[i], bb[j], acc[i][j]);
        }
    }

    // LoRA-B epilogue
    __syncthreads();
    *(float4*)&Ts[lr][lc]      = *(const float4*)&Tb[(size_t)(m0 + lr)      * RL + lc];
    *(float4*)&Ts[lr+64][lc]   = *(const float4*)&Tb[(size_t)(m0 + lr + 64) * RL + lc];
    *(float4*)&Us[lr][lc]      = *(const float4*)&Ub[(size_t)(n0 + lr)      * RL + lc];
    *(float4*)&Us[lr+64][lc]   = *(const float4*)&Ub[(size_t)(n0 + lr + 64) * RL + lc];
    __syncthreads();

#pragma unroll
    for (int i = 0; i < 8; i++) {
        int mi = (i < 4) ? (ty*4 + i) : (64 + ty*4 + i - 4);
        float tv[RL];
#pragma unroll
        for (int r = 0; r < RL; r++) tv[r] = Ts[mi][r];
        float o[8];
#pragma unroll
        for (int j = 0; j < 8; j++) {
            int nj = (j < 4) ? (tx*4 + j) : (64 + tx*4 + j - 4);
            float s = acc[i][j];
#pragma unroll
            for (int r = 0; r < RL; r++) s = fmaf(tv[r], Us[nj][r], s);
            o[j] = s;
        }
        size_t base = (size_t)(m0 + mi) * N + n0;
        *(float4*)&Cb[base + tx*4]      = make_float4(o[0], o[1], o[2], o[3]);
        *(float4*)&Cb[base + 64 + tx*4] = make_float4(o[4], o[5], o[6], o[7]);
    }
}

// ---------------- RoPE in-place ---------------------------------------------
__global__ void rope_kernel(float* __restrict__ p, int nheads) {
    int idx = blockIdx.x * blockDim.x + threadIdx.x;
    int total = BB * SEQ * nheads * (DH/2);
    if (idx >= total) return;
    int j = idx & 63;
    int h = (idx >> 6) % nheads;
    int s = (idx / (64 * nheads)) % SEQ;
    int b = idx / (64 * nheads * SEQ);
    size_t base = (((size_t)(b * SEQ + s)) * nheads + h) * DH;
    float c  = g_cos[s * 64 + j];
    float sn = g_sin[s * 64 + j];
    float x1 = p[base + j];
    float x2 = p[base + j + 64];
    p[base + j]      = fmaf(x1, c, -x2 * sn);
    p[base + j + 64] = fmaf(x2, c,  x1 * sn);
}

// ---------------- Flash attention (fp32, causal, GQA) -----------------------
struct AttnSmem {
    float Qs[64][129];
    float Ks[64][129];   // reused for V
    float Ps[64][65];
    float mrow[64];
    float lrow[64];
    float arow[64];
};

__global__ __launch_bounds__(256) void attn_kernel() {
    extern __shared__ char smem_raw[];
    AttnSmem& sm = *reinterpret_cast<AttnSmem*>(smem_raw);

    const int qt = blockIdx.x;       // query tile (64 rows)
    const int h  = blockIdx.y;
    const int b  = blockIdx.z;
    const int hk = h >> 2;           // NH/NKV = 4
    const int tid = threadIdx.x;
    const int tx = tid & 15, ty = tid >> 4;
    const int rv = tid >> 2;         // PV row owner 0..63
    const int cg = tid & 3;          // PV col group

    const float scale = 0.08838834764831845f;   // 1/sqrt(128)

    // load Q tile, pre-scaled
    {
        int r = tid >> 2;
        int dbase = (tid & 3) * 32;
        size_t gb = (((size_t)(b * SEQ + qt * 64 + r)) * NH + h) * DH + dbase;
#pragma unroll
        for (int u = 0; u < 8; u++) {
            float4 v4 = *(const float4*)&g_q[gb + u * 4];
            sm.Qs[r][dbase + u*4 + 0] = v4.x * scale;
            sm.Qs[r][dbase + u*4 + 1] = v4.y * scale;
            sm.Qs[r][dbase + u*4 + 2] = v4.z * scale;
            sm.Qs[r][dbase + u*4 + 3] = v4.w * scale;
        }
    }
    if (tid < 64) { sm.mrow[tid] = -1e30f; sm.lrow[tid] = 0.f; }

    float o[32];
#pragma unroll
    for (int t = 0; t < 32; t++) o[t] = 0.f;

    for (int jt = 0; jt <= qt; jt++) {
        __syncthreads();   // Qs ready / previous PV done with Ks
        // load K tile
        {
            int r = tid >> 2;
            int dbase = (tid & 3) * 32;
            size_t gb = (((size_t)(b * SEQ + jt * 64 + r)) * NKV + hk) * DH + dbase;
#pragma unroll
            for (int u = 0; u < 8; u++) {
                float4 v4 = *(const float4*)&g_k[gb + u * 4];
                sm.Ks[r][dbase + u*4 + 0] = v4.x;
                sm.Ks[r][dbase + u*4 + 1] = v4.y;
                sm.Ks[r][dbase + u*4 + 2] = v4.z;
                sm.Ks[r][dbase + u*4 + 3] = v4.w;
            }
        }
        __syncthreads();

        // S = Q K^T (scaled), 4x4 per thread
        float sacc[4][4];
#pragma unroll
        for (int i = 0; i < 4; i++)
#pragma unroll
            for (int j = 0; j < 4; j++) sacc[i][j] = 0.f;
#pragma unroll 4
        for (int d = 0; d < DH; d++) {
            float a[4], bb[4];
#pragma unroll
            for (int i = 0; i < 4; i++) a[i]  = sm.Qs[ty*4 + i][d];
#pragma unroll
            for (int j = 0; j < 4; j++) bb[j] = sm.Ks[tx*4 + j][d];
#pragma unroll
            for (int i = 0; i < 4; i++)
#pragma unroll
                for (int j = 0; j < 4; j++)
                    sacc[i][j] = fmaf(a[i], bb[j], sacc[i][j]);
        }
        // mask + write P
#pragma unroll
        for (int i = 0; i < 4; i++) {
            int sg = qt * 64 + ty*4 + i;
#pragma unroll
            for (int j = 0; j < 4; j++) {
                int cgl = jt * 64 + tx*4 + j;
                sm.Ps[ty*4 + i][tx*4 + j] = (cgl <= sg) ? sacc[i][j] : -1e30f;
            }
        }
        __syncthreads();

        // online softmax per row
        if (tid < 64) {
            int r = tid;
            float mo = sm.mrow[r];
            float mx = mo;
#pragma unroll 8
            for (int c = 0; c < 64; c++) mx = fmaxf(mx, sm.Ps[r][c]);
            float al = __expf(mo - mx);
            float sum = 0.f;
#pragma unroll 8
            for (int c = 0; c < 64; c++) {
                float pv = __expf(sm.Ps[r][c] - mx);
                sm.Ps[r][c] = pv;
                sum += pv;
            }
            sm.lrow[r] = sm.lrow[r] * al + sum;
            sm.mrow[r] = mx;
            sm.arow[r] = al;
        }
        __syncthreads();

        // rescale accumulators
        float al = sm.arow[rv];
#pragma unroll
        for (int t = 0; t < 32; t++) o[t] *= al;

        // load V tile into Ks
        {
            int r = tid >> 2;
            int dbase = (tid & 3) * 32;
            size_t gb = (((size_t)(b * SEQ + jt * 64 + r)) * NKV + hk) * DH + dbase;
#pragma unroll
            for (int u = 0; u < 8; u++) {
                float4 v4 = *(const float4*)&g_v[gb + u * 4];
                sm.Ks[r][dbase + u*4 + 0] = v4.x;
                sm.Ks[r][dbase + u*4 + 1] = v4.y;
                sm.Ks[r][dbase + u*4 + 2] = v4.z;
                sm.Ks[r][dbase + u*4 + 3] = v4.w;
            }
        }
        __syncthreads();

        // O += P @ V  (thread owns row rv, interleaved cols cg + 4t)
#pragma unroll 4
        for (int j = 0; j < 64; j++) {
            float pv = sm.Ps[rv][j];
#pragma unroll
            for (int t = 0; t < 32; t++)
                o[t] = fmaf(pv, sm.Ks[j][cg + 4*t], o[t]);
        }
    }

    // final normalize + write
    float linv = 1.f / sm.lrow[rv];
    size_t gb = (((size_t)(b * SEQ + qt * 64 + rv)) * NH + h) * DH;
#pragma unroll
    for (int t = 0; t < 32; t++)
        g_attn[gb + cg + 4*t] = o[t] * linv;
}

// ---------------- launcher ---------------------------------------------------
extern "C" void kernel_launch(void* const* d_in, const int* in_sizes, int n_in,
                              void* d_out, int out_size) {
    const float* x  = (const float*)d_in[0];
    const float* Wq = (const float*)d_in[1];
    const float* Wk = (const float*)d_in[2];
    const float* Wv = (const float*)d_in[3];
    const float* Wo = (const float*)d_in[4];
    const float* Aq = (const float*)d_in[5];
    const float* Bq = (const float*)d_in[6];
    const float* Ak = (const float*)d_in[7];
    const float* Bk = (const float*)d_in[8];
    const float* Av = (const float*)d_in[9];
    const float* Bv = (const float*)d_in[10];
    const float* Ao = (const float*)d_in[11];
    const float* Bo = (const float*)d_in[12];
    float* out = (float*)d_out;

    float *q_ptr, *k_ptr, *v_ptr, *attn_ptr, *t_ptr;
    cudaGetSymbolAddress((void**)&q_ptr, g_q);
    cudaGetSymbolAddress((void**)&k_ptr, g_k);
    cudaGetSymbolAddress((void**)&v_ptr, g_v);
    cudaGetSymbolAddress((void**)&attn_ptr, g_attn);
    cudaGetSymbolAddress((void**)&t_ptr, g_t);

    cudaFuncSetAttribute(attn_kernel,
                         cudaFuncAttributeMaxDynamicSharedMemorySize,
                         (int)sizeof(AttnSmem));

    // RoPE tables
    rope_tables_kernel<<<(SEQ*(DH/2) + 255)/256, 256>>>();

    // Q = x @ Wq^T + lora
    lora_a_kernel<<<BB*SEQ, 128>>>(x, Aq, t_ptr, HIDDEN);
    gemm_lora_kernel<<<dim3(QDIM/128, SEQ/128, BB), 256>>>(x, Wq, t_ptr, Bq, q_ptr, QDIM, HIDDEN);

    // K
    lora_a_kernel<<<BB*SEQ, 128>>>(x, Ak, t_ptr, HIDDEN);
    gemm_lora_kernel<<<dim3(KVDIM/128, SEQ/128, BB), 256>>>(x, Wk, t_ptr, Bk, k_ptr, KVDIM, HIDDEN);

    // V
    lora_a_kernel<<<BB*SEQ, 128>>>(x, Av, t_ptr, HIDDEN);
    gemm_lora_kernel<<<dim3(KVDIM/128, SEQ/128, BB), 256>>>(x, Wv, t_ptr, Bv, v_ptr, KVDIM, HIDDEN);

    // RoPE
    {
        int tq = BB*SEQ*NH*(DH/2);
        rope_kernel<<<(tq + 255)/256, 256>>>(q_ptr, NH);
        int tk = BB*SEQ*NKV*(DH/2);
        rope_kernel<<<(tk + 255)/256, 256>>>(k_ptr, NKV);
    }

    // Attention
    attn_kernel<<<dim3(SEQ/64, NH, BB), 256, sizeof(AttnSmem)>>>();

    // Output projection
    lora_a_kernel<<<BB*SEQ, 128>>>(attn_ptr, Ao, t_ptr, QDIM);
    gemm_lora_kernel<<<dim3(HIDDEN/128, SEQ/128, BB), 256>>>(attn_ptr, Wo, t_ptr, Bo, out, HIDDEN, QDIM);
}

// round 2
// speedup vs baseline: 2.2678x; 2.2678x over previous
#include <cuda_runtime.h>
#include <math.h>
#include <stdint.h>

#define BB 4
#define SEQ 1024
#define HIDDEN 4096
#define NH 32
#define NKV 8
#define DH 128
#define RL 16
#define QDIM (NH*DH)     // 4096
#define KVDIM (NKV*DH)   // 1024

// ---------------- scratch (device globals; no allocations allowed) ----------
__device__ float g_q[(size_t)BB*SEQ*QDIM];
__device__ float g_k[(size_t)BB*SEQ*KVDIM];
__device__ float g_v[(size_t)BB*SEQ*KVDIM];
__device__ float g_attn[(size_t)BB*SEQ*QDIM];
__device__ float g_t[(size_t)BB*SEQ*RL];
__device__ float g_cos[SEQ*(DH/2)];
__device__ float g_sin[SEQ*(DH/2)];

// ---------------- helpers ----------------------------------------------------
__device__ __forceinline__ uint32_t f2tf(float x) {
    uint32_t r;
    asm("cvt.rna.tf32.f32 %0, %1;" : "=r"(r) : "f"(x));
    return r;
}

#define MMA_TF32(c0,c1,c2,c3,a0,a1,a2,a3,b0,b1)                              \
    asm volatile("mma.sync.aligned.m16n8k8.row.col.f32.tf32.tf32.f32 "       \
        "{%0,%1,%2,%3}, {%4,%5,%6,%7}, {%8,%9}, {%0,%1,%2,%3};"              \
        : "+f"(c0),"+f"(c1),"+f"(c2),"+f"(c3)                                \
        : "r"(a0),"r"(a1),"r"(a2),"r"(a3),"r"(b0),"r"(b1))

// ---------------- RoPE tables ----------------------------------------------
__global__ void rope_tables_kernel() {
    int idx = blockIdx.x * blockDim.x + threadIdx.x;
    if (idx >= SEQ * (DH/2)) return;
    int s = idx / (DH/2);
    int j = idx % (DH/2);
    float e = -(float)j * (13.287712379549449f / 64.0f);
    float inv = exp2f(e);
    float ang = (float)s * inv;
    g_cos[idx] = cosf(ang);
    g_sin[idx] = sinf(ang);
}

// ---------------- LoRA A-side: t[b,s,r] = sum_i x[b,s,i] * A[b,r,i] ---------
// 4 rows per block (g = tid>>6 picks the row) so A is shared through L1/L2.
__global__ __launch_bounds__(256) void lora_a_kernel(
    const float* __restrict__ x, const float* __restrict__ A,
    float* __restrict__ t, int K)
{
    const int g = threadIdx.x >> 6;
    const int j = threadIdx.x & 63;
    const int row = blockIdx.x * 4 + g;
    const int b = row / SEQ;
    const float* xr = x + (size_t)row * K;
    const float* Ab = A + (size_t)b * RL * K;

    float acc[RL];
#pragma unroll
    for (int r = 0; r < RL; r++) acc[r] = 0.f;

    for (int k = j * 4; k < K; k += 256) {
        float4 xv = *(const float4*)(xr + k);
#pragma unroll
        for (int r = 0; r < RL; r++) {
            float4 av = *(const float4*)(Ab + (size_t)r * K + k);
            float s = fmaf(xv.x, av.x, fmaf(xv.y, av.y, fmaf(xv.z, av.z, xv.w * av.w)));
            acc[r] += s;
        }
    }

    __shared__ float red[4][64][17];
#pragma unroll
    for (int r = 0; r < RL; r++) red[g][j][r] = acc[r];
    __syncthreads();
    if (j < RL) {
        float s = 0.f;
#pragma unroll 8
        for (int jj = 0; jj < 64; jj++) s += red[g][jj][j];
        t[(size_t)row * RL + j] = s;
    }
}

// ---------------- tf32 MMA GEMM + LoRA-B epilogue ----------------------------
// C[b] (SEQ x N) = X[b] (SEQ x K) @ W^T  + T[b] (SEQ x 16) @ BL[b]^T
// Block tile 128x128, K-tile 32. 8 warps: warp tile 32(M) x 64(N).
#define BM 128
#define BN 128
#define BK 32
#define KPAD 36

__global__ __launch_bounds__(256, 2) void gemm_lora_tf32(
    const float* __restrict__ X, const float* __restrict__ W,
    const float* __restrict__ T, const float* __restrict__ BL,
    float* __restrict__ C, int N, int K)
{
    __shared__ uint32_t As[BM][KPAD];   // X tile, [m][k], tf32 bits
    __shared__ uint32_t Bs[BN][KPAD];   // W tile, [n][k], tf32 bits

    const int b  = blockIdx.z;
    const int n0 = blockIdx.x * BN;
    const int m0 = blockIdx.y * BM;
    const float* Xb = X + (size_t)b * SEQ * K;
    const float* Tb = T + (size_t)b * SEQ * RL;
    const float* Ub = BL + (size_t)b * N * RL;
    float* Cb = C + (size_t)b * SEQ * N;

    const int tid  = threadIdx.x;
    const int warp = tid >> 5;
    const int lane = tid & 31;
    const int wm = (warp & 3) * 32;    // warp m offset
    const int wn = (warp >> 2) * 64;   // warp n offset
    const int gid = lane >> 2;         // 0..7
    const int tig = lane & 3;          // 0..3

    float acc[2][8][4];
#pragma unroll
    for (int mf = 0; mf < 2; mf++)
#pragma unroll
        for (int nf = 0; nf < 8; nf++)
#pragma unroll
            for (int c = 0; c < 4; c++) acc[mf][nf][c] = 0.f;

    // global load mapping: 4 float4 per thread per operand per K-tile
    // f = tid + i*256; row = f>>3 (0..127), kc = (f&7)*4
    for (int k0 = 0; k0 < K; k0 += BK) {
        float4 xv[4], wv[4];
#pragma unroll
        for (int i = 0; i < 4; i++) {
            int f = tid + i * 256;
            int row = f >> 3;
            int kc = (f & 7) * 4;
            xv[i] = *(const float4*)(Xb + (size_t)(m0 + row) * K + k0 + kc);
            wv[i] = *(const float4*)(W  + (size_t)(n0 + row) * K + k0 + kc);
        }
        __syncthreads();
#pragma unroll
        for (int i = 0; i < 4; i++) {
            int f = tid + i * 256;
            int row = f >> 3;
            int kc = (f & 7) * 4;
            As[row][kc+0] = f2tf(xv[i].x); As[row][kc+1] = f2tf(xv[i].y);
            As[row][kc+2] = f2tf(xv[i].z); As[row][kc+3] = f2tf(xv[i].w);
            Bs[row][kc+0] = f2tf(wv[i].x); Bs[row][kc+1] = f2tf(wv[i].y);
            Bs[row][kc+2] = f2tf(wv[i].z); Bs[row][kc+3] = f2tf(wv[i].w);
        }
        __syncthreads();

#pragma unroll
        for (int ks = 0; ks < 4; ks++) {
            const int kb = ks * 8;
            uint32_t a[2][4];
#pragma unroll
            for (int mf = 0; mf < 2; mf++) {
                int mrow = wm + mf * 16 + gid;
                a[mf][0] = As[mrow][kb + tig];
                a[mf][1] = As[mrow + 8][kb + tig];
                a[mf][2] = As[mrow][kb + tig + 4];
                a[mf][3] = As[mrow + 8][kb + tig + 4];
            }
#pragma unroll
            for (int nf = 0; nf < 8; nf++) {
                int nrow = wn + nf * 8 + gid;
                uint32_t b0 = Bs[nrow][kb + tig];
                uint32_t b1 = Bs[nrow][kb + tig + 4];
                MMA_TF32(acc[0][nf][0], acc[0][nf][1], acc[0][nf][2], acc[0][nf][3],
                         a[0][0], a[0][1], a[0][2], a[0][3], b0, b1);
                MMA_TF32(acc[1][nf][0], acc[1][nf][1], acc[1][nf][2], acc[1][nf][3],
                         a[1][0], a[1][1], a[1][2], a[1][3], b0, b1);
            }
        }
    }

    // ---- LoRA-B epilogue: reuse As/Bs smem for T and U (fp32 exact) ----
    __syncthreads();
    float* Ts = (float*)&As[0][0];   // [128][16]
    float* Us = (float*)&Bs[0][0];   // [128][16]
#pragma unroll
    for (int i = 0; i < 2; i++) {
        int f4 = tid + i * 256;      // 0..511
        int row = f4 >> 2;
        int c4 = (f4 & 3) * 4;
        *(float4*)&Ts[row * RL + c4] = *(const float4*)&Tb[(size_t)(m0 + row) * RL + c4];
        *(float4*)&Us[row * RL + c4] = *(const float4*)&Ub[(size_t)(n0 + row) * RL + c4];
    }
    __syncthreads();

#pragma unroll
    for (int mf = 0; mf < 2; mf++) {
#pragma unroll
        for (int rr = 0; rr < 2; rr++) {
            int m_local = wm + mf * 16 + rr * 8 + gid;
            float tv[RL];
#pragma unroll
            for (int r = 0; r < RL; r++) tv[r] = Ts[m_local * RL + r];
            size_t crow = (size_t)(m0 + m_local) * N + n0;
#pragma unroll
            for (int nf = 0; nf < 8; nf++) {
                int n_local = wn + nf * 8 + 2 * tig;
                float s0 = acc[mf][nf][rr * 2 + 0];
                float s1 = acc[mf][nf][rr * 2 + 1];
#pragma unroll
                for (int r = 0; r < RL; r++) {
                    s0 = fmaf(tv[r], Us[n_local * RL + r], s0);
                    s1 = fmaf(tv[r], Us[(n_local + 1) * RL + r], s1);
                }
                *(float2*)&Cb[crow + n_local] = make_float2(s0, s1);
            }
        }
    }
}

// ---------------- RoPE in-place ---------------------------------------------
__global__ void rope_kernel(float* __restrict__ p, int nheads) {
    int idx = blockIdx.x * blockDim.x + threadIdx.x;
    int total = BB * SEQ * nheads * (DH/2);
    if (idx >= total) return;
    int j = idx & 63;
    int h = (idx >> 6) % nheads;
    int s = (idx / (64 * nheads)) % SEQ;
    int b = idx / (64 * nheads * SEQ);
    size_t base = (((size_t)(b * SEQ + s)) * nheads + h) * DH;
    float c  = g_cos[s * 64 + j];
    float sn = g_sin[s * 64 + j];
    float x1 = p[base + j];
    float x2 = p[base + j + 64];
    p[base + j]      = fmaf(x1, c, -x2 * sn);
    p[base + j + 64] = fmaf(x2, c,  x1 * sn);
}

// ---------------- Flash attention (fp32, causal, GQA) -----------------------
struct AttnSmem {
    float Qs[64][129];
    float Ks[64][129];   // reused for V
    float Ps[64][65];
    float mrow[64];
    float lrow[64];
    float arow[64];
};

__global__ __launch_bounds__(256) void attn_kernel() {
    extern __shared__ char smem_raw[];
    AttnSmem& sm = *reinterpret_cast<AttnSmem*>(smem_raw);

    const int qt = blockIdx.x;
    const int h  = blockIdx.y;
    const int b  = blockIdx.z;
    const int hk = h >> 2;
    const int tid = threadIdx.x;
    const int tx = tid & 15, ty = tid >> 4;
    const int rv = tid >> 2;
    const int cg = tid & 3;

    const float scale = 0.08838834764831845f;

    {
        int r = tid >> 2;
        int dbase = (tid & 3) * 32;
        size_t gb = (((size_t)(b * SEQ + qt * 64 + r)) * NH + h) * DH + dbase;
#pragma unroll
        for (int u = 0; u < 8; u++) {
            float4 v4 = *(const float4*)&g_q[gb + u * 4];
            sm.Qs[r][dbase + u*4 + 0] = v4.x * scale;
            sm.Qs[r][dbase + u*4 + 1] = v4.y * scale;
            sm.Qs[r][dbase + u*4 + 2] = v4.z * scale;
            sm.Qs[r][dbase + u*4 + 3] = v4.w * scale;
        }
    }
    if (tid < 64) { sm.mrow[tid] = -1e30f; sm.lrow[tid] = 0.f; }

    float o[32];
#pragma unroll
    for (int t = 0; t < 32; t++) o[t] = 0.f;

    for (int jt = 0; jt <= qt; jt++) {
        __syncthreads();
        {
            int r = tid >> 2;
            int dbase = (tid & 3) * 32;
            size_t gb = (((size_t)(b * SEQ + jt * 64 + r)) * NKV + hk) * DH + dbase;
#pragma unroll
            for (int u = 0; u < 8; u++) {
                float4 v4 = *(const float4*)&g_k[gb + u * 4];
                sm.Ks[r][dbase + u*4 + 0] = v4.x;
                sm.Ks[r][dbase + u*4 + 1] = v4.y;
                sm.Ks[r][dbase + u*4 + 2] = v4.z;
                sm.Ks[r][dbase + u*4 + 3] = v4.w;
            }
        }
        __syncthreads();

        float sacc[4][4];
#pragma unroll
        for (int i = 0; i < 4; i++)
#pragma unroll
            for (int j = 0; j < 4; j++) sacc[i][j] = 0.f;
#pragma unroll 4
        for (int d = 0; d < DH; d++) {
            float a[4], bb[4];
#pragma unroll
            for (int i = 0; i < 4; i++) a[i]  = sm.Qs[ty*4 + i][d];
#pragma unroll
            for (int j = 0; j < 4; j++) bb[j] = sm.Ks[tx*4 + j][d];
#pragma unroll
            for (int i = 0; i < 4; i++)
#pragma unroll
                for (int j = 0; j < 4; j++)
                    sacc[i][j] = fmaf(a[i], bb[j], sacc[i][j]);
        }
#pragma unroll
        for (int i = 0; i < 4; i++) {
            int sg = qt * 64 + ty*4 + i;
#pragma unroll
            for (int j = 0; j < 4; j++) {
                int cgl = jt * 64 + tx*4 + j;
                sm.Ps[ty*4 + i][tx*4 + j] = (cgl <= sg) ? sacc[i][j] : -1e30f;
            }
        }
        __syncthreads();

        if (tid < 64) {
            int r = tid;
            float mo = sm.mrow[r];
            float mx = mo;
#pragma unroll 8
            for (int c = 0; c < 64; c++) mx = fmaxf(mx, sm.Ps[r][c]);
            float al = __expf(mo - mx);
            float sum = 0.f;
#pragma unroll 8
            for (int c = 0; c < 64; c++) {
                float pv = __expf(sm.Ps[r][c] - mx);
                sm.Ps[r][c] = pv;
                sum += pv;
            }
            sm.lrow[r] = sm.lrow[r] * al + sum;
            sm.mrow[r] = mx;
            sm.arow[r] = al;
        }
        __syncthreads();

        float al = sm.arow[rv];
#pragma unroll
        for (int t = 0; t < 32; t++) o[t] *= al;

        {
            int r = tid >> 2;
            int dbase = (tid & 3) * 32;
            size_t gb = (((size_t)(b * SEQ + jt * 64 + r)) * NKV + hk) * DH + dbase;
#pragma unroll
            for (int u = 0; u < 8; u++) {
                float4 v4 = *(const float4*)&g_v[gb + u * 4];
                sm.Ks[r][dbase + u*4 + 0] = v4.x;
                sm.Ks[r][dbase + u*4 + 1] = v4.y;
                sm.Ks[r][dbase + u*4 + 2] = v4.z;
                sm.Ks[r][dbase + u*4 + 3] = v4.w;
            }
        }
        __syncthreads();

#pragma unroll 4
        for (int j = 0; j < 64; j++) {
            float pv = sm.Ps[rv][j];
#pragma unroll
            for (int t = 0; t < 32; t++)
                o[t] = fmaf(pv, sm.Ks[j][cg + 4*t], o[t]);
        }
    }

    float linv = 1.f / sm.lrow[rv];
    size_t gb = (((size_t)(b * SEQ + qt * 64 + rv)) * NH + h) * DH;
#pragma unroll
    for (int t = 0; t < 32; t++)
        g_attn[gb + cg + 4*t] = o[t] * linv;
}

// ---------------- launcher ---------------------------------------------------
extern "C" void kernel_launch(void* const* d_in, const int* in_sizes, int n_in,
                              void* d_out, int out_size) {
    const float* x  = (const float*)d_in[0];
    const float* Wq = (const float*)d_in[1];
    const float* Wk = (const float*)d_in[2];
    const float* Wv = (const float*)d_in[3];
    const float* Wo = (const float*)d_in[4];
    const float* Aq = (const float*)d_in[5];
    const float* Bq = (const float*)d_in[6];
    const float* Ak = (const float*)d_in[7];
    const float* Bk = (const float*)d_in[8];
    const float* Av = (const float*)d_in[9];
    const float* Bv = (const float*)d_in[10];
    const float* Ao = (const float*)d_in[11];
    const float* Bo = (const float*)d_in[12];
    float* out = (float*)d_out;

    float *q_ptr, *k_ptr, *v_ptr, *attn_ptr, *t_ptr;
    cudaGetSymbolAddress((void**)&q_ptr, g_q);
    cudaGetSymbolAddress((void**)&k_ptr, g_k);
    cudaGetSymbolAddress((void**)&v_ptr, g_v);
    cudaGetSymbolAddress((void**)&attn_ptr, g_attn);
    cudaGetSymbolAddress((void**)&t_ptr, g_t);

    cudaFuncSetAttribute(attn_kernel,
                         cudaFuncAttributeMaxDynamicSharedMemorySize,
                         (int)sizeof(AttnSmem));

    rope_tables_kernel<<<(SEQ*(DH/2) + 255)/256, 256>>>();

    // Q
    lora_a_kernel<<<BB*SEQ/4, 256>>>(x, Aq, t_ptr, HIDDEN);
    gemm_lora_tf32<<<dim3(QDIM/BN, SEQ/BM, BB), 256>>>(x, Wq, t_ptr, Bq, q_ptr, QDIM, HIDDEN);

    // K
    lora_a_kernel<<<BB*SEQ/4, 256>>>(x, Ak, t_ptr, HIDDEN);
    gemm_lora_tf32<<<dim3(KVDIM/BN, SEQ/BM, BB), 256>>>(x, Wk, t_ptr, Bk, k_ptr, KVDIM, HIDDEN);

    // V
    lora_a_kernel<<<BB*SEQ/4, 256>>>(x, Av, t_ptr, HIDDEN);
    gemm_lora_tf32<<<dim3(KVDIM/BN, SEQ/BM, BB), 256>>>(x, Wv, t_ptr, Bv, v_ptr, KVDIM, HIDDEN);

    // RoPE
    {
        int tq = BB*SEQ*NH*(DH/2);
        rope_kernel<<<(tq + 255)/256, 256>>>(q_ptr, NH);
        int tk = BB*SEQ*NKV*(DH/2);
        rope_kernel<<<(tk + 255)/256, 256>>>(k_ptr, NKV);
    }

    // Attention
    attn_kernel<<<dim3(SEQ/64, NH, BB), 256, sizeof(AttnSmem)>>>();

    // Output projection
    lora_a_kernel<<<BB*SEQ/4, 256>>>(attn_ptr, Ao, t_ptr, QDIM);
    gemm_lora_tf32<<<dim3(HIDDEN/BN, SEQ/BM, BB), 256>>>(attn_ptr, Wo, t_ptr, Bo, out, HIDDEN, QDIM);
}

// round 3
// speedup vs baseline: 2.9513x; 1.3014x over previous
#include <cuda_runtime.h>
#include <math.h>
#include <stdint.h>

#define BB 4
#define SEQ 1024
#define HIDDEN 4096
#define NH 32
#define NKV 8
#define DH 128
#define RL 16
#define QDIM (NH*DH)     // 4096
#define KVDIM (NKV*DH)   // 1024

// ---------------- scratch (device globals; no allocations allowed) ----------
__device__ float g_q[(size_t)BB*SEQ*QDIM];
__device__ float g_k[(size_t)BB*SEQ*KVDIM];
__device__ float g_v[(size_t)BB*SEQ*KVDIM];
__device__ float g_attn[(size_t)BB*SEQ*QDIM];
__device__ float g_t[(size_t)BB*SEQ*RL];
__device__ float g_cos[SEQ*(DH/2)];
__device__ float g_sin[SEQ*(DH/2)];

// ---------------- helpers ----------------------------------------------------
__device__ __forceinline__ uint32_t f2tf(float x) {
    uint32_t r;
    asm("cvt.rna.tf32.f32 %0, %1;" : "=r"(r) : "f"(x));
    return r;
}

#define MMA_TF32(c0,c1,c2,c3,a0,a1,a2,a3,b0,b1)                              \
    asm volatile("mma.sync.aligned.m16n8k8.row.col.f32.tf32.tf32.f32 "       \
        "{%0,%1,%2,%3}, {%4,%5,%6,%7}, {%8,%9}, {%0,%1,%2,%3};"              \
        : "+f"(c0),"+f"(c1),"+f"(c2),"+f"(c3)                                \
        : "r"(a0),"r"(a1),"r"(a2),"r"(a3),"r"(b0),"r"(b1))

// ---------------- RoPE tables ----------------------------------------------
__global__ void rope_tables_kernel() {
    int idx = blockIdx.x * blockDim.x + threadIdx.x;
    if (idx >= SEQ * (DH/2)) return;
    int s = idx / (DH/2);
    int j = idx % (DH/2);
    float e = -(float)j * (13.287712379549449f / 64.0f);
    float inv = exp2f(e);
    float ang = (float)s * inv;
    g_cos[idx] = cosf(ang);
    g_sin[idx] = sinf(ang);
}

// ---------------- LoRA A-side ------------------------------------------------
__global__ __launch_bounds__(256) void lora_a_kernel(
    const float* __restrict__ x, const float* __restrict__ A,
    float* __restrict__ t, int K)
{
    const int g = threadIdx.x >> 6;
    const int j = threadIdx.x & 63;
    const int row = blockIdx.x * 4 + g;
    const int b = row / SEQ;
    const float* xr = x + (size_t)row * K;
    const float* Ab = A + (size_t)b * RL * K;

    float acc[RL];
#pragma unroll
    for (int r = 0; r < RL; r++) acc[r] = 0.f;

    for (int k = j * 4; k < K; k += 256) {
        float4 xv = *(const float4*)(xr + k);
#pragma unroll
        for (int r = 0; r < RL; r++) {
            float4 av = *(const float4*)(Ab + (size_t)r * K + k);
            float s = fmaf(xv.x, av.x, fmaf(xv.y, av.y, fmaf(xv.z, av.z, xv.w * av.w)));
            acc[r] += s;
        }
    }

    __shared__ float red[4][64][17];
#pragma unroll
    for (int r = 0; r < RL; r++) red[g][j][r] = acc[r];
    __syncthreads();
    if (j < RL) {
        float s = 0.f;
#pragma unroll 8
        for (int jj = 0; jj < 64; jj++) s += red[g][jj][j];
        t[(size_t)row * RL + j] = s;
    }
}

// ---------------- tf32 MMA GEMM + LoRA-B epilogue ----------------------------
#define BM 128
#define BN 128
#define BK 32
#define KPAD 36

__global__ __launch_bounds__(256, 2) void gemm_lora_tf32(
    const float* __restrict__ X, const float* __restrict__ W,
    const float* __restrict__ T, const float* __restrict__ BL,
    float* __restrict__ C, int N, int K)
{
    __shared__ uint32_t As[BM][KPAD];
    __shared__ uint32_t Bs[BN][KPAD];

    const int b  = blockIdx.z;
    const int n0 = blockIdx.x * BN;
    const int m0 = blockIdx.y * BM;
    const float* Xb = X + (size_t)b * SEQ * K;
    const float* Tb = T + (size_t)b * SEQ * RL;
    const float* Ub = BL + (size_t)b * N * RL;
    float* Cb = C + (size_t)b * SEQ * N;

    const int tid  = threadIdx.x;
    const int warp = tid >> 5;
    const int lane = tid & 31;
    const int wm = (warp & 3) * 32;
    const int wn = (warp >> 2) * 64;
    const int gid = lane >> 2;
    const int tig = lane & 3;

    float acc[2][8][4];
#pragma unroll
    for (int mf = 0; mf < 2; mf++)
#pragma unroll
        for (int nf = 0; nf < 8; nf++)
#pragma unroll
            for (int c = 0; c < 4; c++) acc[mf][nf][c] = 0.f;

    for (int k0 = 0; k0 < K; k0 += BK) {
        float4 xv[4], wv[4];
#pragma unroll
        for (int i = 0; i < 4; i++) {
            int f = tid + i * 256;
            int row = f >> 3;
            int kc = (f & 7) * 4;
            xv[i] = *(const float4*)(Xb + (size_t)(m0 + row) * K + k0 + kc);
            wv[i] = *(const float4*)(W  + (size_t)(n0 + row) * K + k0 + kc);
        }
        __syncthreads();
#pragma unroll
        for (int i = 0; i < 4; i++) {
            int f = tid + i * 256;
            int row = f >> 3;
            int kc = (f & 7) * 4;
            As[row][kc+0] = f2tf(xv[i].x); As[row][kc+1] = f2tf(xv[i].y);
            As[row][kc+2] = f2tf(xv[i].z); As[row][kc+3] = f2tf(xv[i].w);
            Bs[row][kc+0] = f2tf(wv[i].x); Bs[row][kc+1] = f2tf(wv[i].y);
            Bs[row][kc+2] = f2tf(wv[i].z); Bs[row][kc+3] = f2tf(wv[i].w);
        }
        __syncthreads();

#pragma unroll
        for (int ks = 0; ks < 4; ks++) {
            const int kb = ks * 8;
            uint32_t a[2][4];
#pragma unroll
            for (int mf = 0; mf < 2; mf++) {
                int mrow = wm + mf * 16 + gid;
                a[mf][0] = As[mrow][kb + tig];
                a[mf][1] = As[mrow + 8][kb + tig];
                a[mf][2] = As[mrow][kb + tig + 4];
                a[mf][3] = As[mrow + 8][kb + tig + 4];
            }
#pragma unroll
            for (int nf = 0; nf < 8; nf++) {
                int nrow = wn + nf * 8 + gid;
                uint32_t b0 = Bs[nrow][kb + tig];
                uint32_t b1 = Bs[nrow][kb + tig + 4];
                MMA_TF32(acc[0][nf][0], acc[0][nf][1], acc[0][nf][2], acc[0][nf][3],
                         a[0][0], a[0][1], a[0][2], a[0][3], b0, b1);
                MMA_TF32(acc[1][nf][0], acc[1][nf][1], acc[1][nf][2], acc[1][nf][3],
                         a[1][0], a[1][1], a[1][2], a[1][3], b0, b1);
            }
        }
    }

    __syncthreads();
    float* Ts = (float*)&As[0][0];
    float* Us = (float*)&Bs[0][0];
#pragma unroll
    for (int i = 0; i < 2; i++) {
        int f4 = tid + i * 256;
        int row = f4 >> 2;
        int c4 = (f4 & 3) * 4;
        *(float4*)&Ts[row * RL + c4] = *(const float4*)&Tb[(size_t)(m0 + row) * RL + c4];
        *(float4*)&Us[row * RL + c4] = *(const float4*)&Ub[(size_t)(n0 + row) * RL + c4];
    }
    __syncthreads();

#pragma unroll
    for (int mf = 0; mf < 2; mf++) {
#pragma unroll
        for (int rr = 0; rr < 2; rr++) {
            int m_local = wm + mf * 16 + rr * 8 + gid;
            float tv[RL];
#pragma unroll
            for (int r = 0; r < RL; r++) tv[r] = Ts[m_local * RL + r];
            size_t crow = (size_t)(m0 + m_local) * N + n0;
#pragma unroll
            for (int nf = 0; nf < 8; nf++) {
                int n_local = wn + nf * 8 + 2 * tig;
                float s0 = acc[mf][nf][rr * 2 + 0];
                float s1 = acc[mf][nf][rr * 2 + 1];
#pragma unroll
                for (int r = 0; r < RL; r++) {
                    s0 = fmaf(tv[r], Us[n_local * RL + r], s0);
                    s1 = fmaf(tv[r], Us[(n_local + 1) * RL + r], s1);
                }
                *(float2*)&Cb[crow + n_local] = make_float2(s0, s1);
            }
        }
    }
}

// ---------------- RoPE in-place ---------------------------------------------
__global__ void rope_kernel(float* __restrict__ p, int nheads) {
    int idx = blockIdx.x * blockDim.x + threadIdx.x;
    int total = BB * SEQ * nheads * (DH/2);
    if (idx >= total) return;
    int j = idx & 63;
    int h = (idx >> 6) % nheads;
    int s = (idx / (64 * nheads)) % SEQ;
    int b = idx / (64 * nheads * SEQ);
    size_t base = (((size_t)(b * SEQ + s)) * nheads + h) * DH;
    float c  = g_cos[s * 64 + j];
    float sn = g_sin[s * 64 + j];
    float x1 = p[base + j];
    float x2 = p[base + j + 64];
    p[base + j]      = fmaf(x1, c, -x2 * sn);
    p[base + j + 64] = fmaf(x2, c,  x1 * sn);
}

// ---------------- Flash attention (split-tf32 MMA, causal, GQA) --------------
// smem layout (bytes):
//  Qhi @ 0       : 64x132 u32 = 33792
//  Qlo @ 33792   : 33792
//  K/V union @ 67584: slot0 (34816): Khi 64x132 / Vhi 128x68
//                     slot1 @ +34816: Klo / Vlo
//  Ps  @ 137216  : 64x68 f32/u32 = 17408
//  mrow/lrow/arow @ 154624 : 3x64 f32
// total 155392
#define ATTN_SMEM 155392
#define QKS 132
#define VSS 68
#define PSS 68
#define SWC(d) ((d) + ((d) >> 5))

__global__ __launch_bounds__(256, 1) void attn_mma_kernel() {
    extern __shared__ char smraw[];
    uint32_t* Qhi = (uint32_t*)(smraw);
    uint32_t* Qlo = (uint32_t*)(smraw + 33792);
    uint32_t* Khi = (uint32_t*)(smraw + 67584);
    uint32_t* Klo = (uint32_t*)(smraw + 67584 + 34816);
    uint32_t* Vhi = Khi;
    uint32_t* Vlo = Klo;
    float*    Psf = (float*)(smraw + 137216);
    uint32_t* Psu = (uint32_t*)Psf;
    float* mrow = (float*)(smraw + 154624);
    float* lrow = mrow + 64;
    float* arow = mrow + 128;

    const int qt = (SEQ/64 - 1) - blockIdx.x;   // heavy tiles first
    const int h  = blockIdx.y;
    const int b  = blockIdx.z;
    const int hk = h >> 2;
    const int tid  = threadIdx.x;
    const int warp = tid >> 5;
    const int lane = tid & 31;
    const int gid = lane >> 2;
    const int tig = lane & 3;
    const int wm  = (warp & 3) * 16;   // S/O row group
    const int wn  = (warp >> 2) * 32;  // S col group
    const int wdn = (warp >> 2) * 64;  // O col group

    const float scale = 0.08838834764831845f;   // 1/sqrt(128)

    // ---- load Q tile (scaled, hi/lo split) ----
    {
        int r = tid >> 2;
        int dbase = (tid & 3) * 32;
        const float* src = g_q + (((size_t)(b * SEQ + qt * 64 + r)) * NH + h) * DH + dbase;
#pragma unroll
        for (int u = 0; u < 8; u++) {
            float4 v4 = *(const float4*)(src + u * 4);
            v4.x *= scale; v4.y *= scale; v4.z *= scale; v4.w *= scale;
            int d = dbase + u * 4;
            int cb = r * QKS + SWC(d);
            uint32_t h0 = f2tf(v4.x), h1 = f2tf(v4.y), h2 = f2tf(v4.z), h3 = f2tf(v4.w);
            Qhi[cb+0] = h0; Qhi[cb+1] = h1; Qhi[cb+2] = h2; Qhi[cb+3] = h3;
            Qlo[cb+0] = f2tf(v4.x - __uint_as_float(h0));
            Qlo[cb+1] = f2tf(v4.y - __uint_as_float(h1));
            Qlo[cb+2] = f2tf(v4.z - __uint_as_float(h2));
            Qlo[cb+3] = f2tf(v4.w - __uint_as_float(h3));
        }
    }
    if (tid < 64) { mrow[tid] = -1e30f; lrow[tid] = 0.f; }
    __syncthreads();

    // ---- preload Qhi a-frags (reused every kv iter) ----
    uint32_t ah[16][4];
#pragma unroll
    for (int ks = 0; ks < 16; ks++) {
        int kb = ks * 8;
        int c = kb + (kb >> 5) + tig;
        ah[ks][0] = Qhi[(wm + gid)     * QKS + c];
        ah[ks][1] = Qhi[(wm + gid + 8) * QKS + c];
        ah[ks][2] = Qhi[(wm + gid)     * QKS + c + 4];
        ah[ks][3] = Qhi[(wm + gid + 8) * QKS + c + 4];
    }

    float o[8][4];
#pragma unroll
    for (int nf = 0; nf < 8; nf++)
#pragma unroll
        for (int c = 0; c < 4; c++) o[nf][c] = 0.f;

    for (int jt = 0; jt <= qt; jt++) {
        __syncthreads();   // prev PV done reading V union

        // ---- load K tile (hi/lo) ----
        {
            int r = tid >> 2;
            int dbase = (tid & 3) * 32;
            const float* src = g_k + (((size_t)(b * SEQ + jt * 64 + r)) * NKV + hk) * DH + dbase;
#pragma unroll
            for (int u = 0; u < 8; u++) {
                float4 v4 = *(const float4*)(src + u * 4);
                int d = dbase + u * 4;
                int cb = r * QKS + SWC(d);
                uint32_t h0 = f2tf(v4.x), h1 = f2tf(v4.y), h2 = f2tf(v4.z), h3 = f2tf(v4.w);
                Khi[cb+0] = h0; Khi[cb+1] = h1; Khi[cb+2] = h2; Khi[cb+3] = h3;
                Klo[cb+0] = f2tf(v4.x - __uint_as_float(h0));
                Klo[cb+1] = f2tf(v4.y - __uint_as_float(h1));
                Klo[cb+2] = f2tf(v4.z - __uint_as_float(h2));
                Klo[cb+3] = f2tf(v4.w - __uint_as_float(h3));
            }
        }
        __syncthreads();

        // ---- S = Q K^T via split tf32 (hi*hi + lo*hi + hi*lo) ----
        float s[4][4];
#pragma unroll
        for (int nf = 0; nf < 4; nf++)
#pragma unroll
            for (int c = 0; c < 4; c++) s[nf][c] = 0.f;

#pragma unroll
        for (int ks = 0; ks < 16; ks++) {
            int kb = ks * 8;
            int c = kb + (kb >> 5) + tig;
            uint32_t al0 = Qlo[(wm + gid)     * QKS + c];
            uint32_t al1 = Qlo[(wm + gid + 8) * QKS + c];
            uint32_t al2 = Qlo[(wm + gid)     * QKS + c + 4];
            uint32_t al3 = Qlo[(wm + gid + 8) * QKS + c + 4];
#pragma unroll
            for (int nf = 0; nf < 4; nf++) {
                int nr = (wn + nf * 8 + gid) * QKS;
                uint32_t bh0 = Khi[nr + c];
                uint32_t bh1 = Khi[nr + c + 4];
                uint32_t bl0 = Klo[nr + c];
                uint32_t bl1 = Klo[nr + c + 4];
                MMA_TF32(s[nf][0], s[nf][1], s[nf][2], s[nf][3],
                         ah[ks][0], ah[ks][1], ah[ks][2], ah[ks][3], bh0, bh1);
                MMA_TF32(s[nf][0], s[nf][1], s[nf][2], s[nf][3],
                         al0, al1, al2, al3, bh0, bh1);
                MMA_TF32(s[nf][0], s[nf][1], s[nf][2], s[nf][3],
                         ah[ks][0], ah[ks][1], ah[ks][2], ah[ks][3], bl0, bl1);
            }
        }

        // ---- write masked S to Ps ----
        {
            int row0 = wm + gid, row1 = row0 + 8;
            int rg0 = qt * 64 + row0, rg1 = qt * 64 + row1;
#pragma unroll
            for (int nf = 0; nf < 4; nf++) {
                int cc = wn + nf * 8 + 2 * tig;
                int cg = jt * 64 + cc;
                float2 w0, w1;
                w0.x = (cg     <= rg0) ? s[nf][0] : -1e30f;
                w0.y = (cg + 1 <= rg0) ? s[nf][1] : -1e30f;
                w1.x = (cg     <= rg1) ? s[nf][2] : -1e30f;
                w1.y = (cg + 1 <= rg1) ? s[nf][3] : -1e30f;
                *(float2*)(Psf + row0 * PSS + cc) = w0;
                *(float2*)(Psf + row1 * PSS + cc) = w1;
            }
        }
        __syncthreads();

        // ---- V global load (in flight during softmax) ----
        int vj = tid & 63;
        int vdc = (tid >> 6) * 32;
        const float* vsrc = g_v + (((size_t)(b * SEQ + jt * 64 + vj)) * NKV + hk) * DH + vdc;
        float4 vv[8];
#pragma unroll
        for (int u = 0; u < 8; u++) vv[u] = *(const float4*)(vsrc + u * 4);

        // ---- online softmax (row split across quad: 16 cols/thread) ----
        {
            int sr = tid >> 2;
            int sc = (tid & 3) * 16;
            float* prow = Psf + sr * PSS + sc;
            float pv[16];
            float mx = -1e30f;
#pragma unroll
            for (int i = 0; i < 16; i++) { pv[i] = prow[i]; mx = fmaxf(mx, pv[i]); }
            mx = fmaxf(mx, __shfl_xor_sync(0xffffffffu, mx, 1));
            mx = fmaxf(mx, __shfl_xor_sync(0xffffffffu, mx, 2));
            float mo = mrow[sr];
            mx = fmaxf(mx, mo);
            float sum = 0.f;
            uint32_t* purow = Psu + sr * PSS + sc;
#pragma unroll
            for (int i = 0; i < 16; i++) {
                float e = __expf(pv[i] - mx);
                sum += e;
                purow[i] = f2tf(e);
            }
            sum += __shfl_xor_sync(0xffffffffu, sum, 1);
            sum += __shfl_xor_sync(0xffffffffu, sum, 2);
            if ((tid & 3) == 0) {
                float alp = __expf(mo - mx);
                lrow[sr] = lrow[sr] * alp + sum;
                mrow[sr] = mx;
                arow[sr] = alp;
            }
        }

        // ---- V store transposed (hi/lo split) into union ----
#pragma unroll
        for (int u = 0; u < 8; u++) {
            int d0 = vdc + u * 4;
            float x0 = vv[u].x, x1 = vv[u].y, x2 = vv[u].z, x3 = vv[u].w;
            uint32_t h0 = f2tf(x0), h1 = f2tf(x1), h2 = f2tf(x2), h3 = f2tf(x3);
            Vhi[(d0+0) * VSS + vj] = h0;
            Vhi[(d0+1) * VSS + vj] = h1;
            Vhi[(d0+2) * VSS + vj] = h2;
            Vhi[(d0+3) * VSS + vj] = h3;
            Vlo[(d0+0) * VSS + vj] = f2tf(x0 - __uint_as_float(h0));
            Vlo[(d0+1) * VSS + vj] = f2tf(x1 - __uint_as_float(h1));
            Vlo[(d0+2) * VSS + vj] = f2tf(x2 - __uint_as_float(h2));
            Vlo[(d0+3) * VSS + vj] = f2tf(x3 - __uint_as_float(h3));
        }
        __syncthreads();

        // ---- rescale O ----
        {
            float a0 = arow[wm + gid];
            float a1 = arow[wm + gid + 8];
#pragma unroll
            for (int nf = 0; nf < 8; nf++) {
                o[nf][0] *= a0; o[nf][1] *= a0;
                o[nf][2] *= a1; o[nf][3] *= a1;
            }
        }

        // ---- O += P @ (Vhi + Vlo) ----
#pragma unroll
        for (int ks = 0; ks < 8; ks++) {
            int kb = ks * 8;
            uint32_t pa0 = Psu[(wm + gid)     * PSS + kb + tig];
            uint32_t pa1 = Psu[(wm + gid + 8) * PSS + kb + tig];
            uint32_t pa2 = Psu[(wm + gid)     * PSS + kb + tig + 4];
            uint32_t pa3 = Psu[(wm + gid + 8) * PSS + kb + tig + 4];
#pragma unroll
            for (int nf = 0; nf < 8; nf++) {
                int dv = (wdn + nf * 8 + gid) * VSS + kb + tig;
                uint32_t bh0 = Vhi[dv], bh1 = Vhi[dv + 4];
                uint32_t bl0 = Vlo[dv], bl1 = Vlo[dv + 4];
                MMA_TF32(o[nf][0], o[nf][1], o[nf][2], o[nf][3],
                         pa0, pa1, pa2, pa3, bh0, bh1);
                MMA_TF32(o[nf][0], o[nf][1], o[nf][2], o[nf][3],
                         pa0, pa1, pa2, pa3, bl0, bl1);
            }
        }
    }

    // ---- epilogue: normalize + write ----
    {
        float li0 = 1.f / lrow[wm + gid];
        float li1 = 1.f / lrow[wm + gid + 8];
        size_t base0 = (((size_t)(b * SEQ + qt * 64 + wm + gid))     * NH + h) * DH;
        size_t base1 = (((size_t)(b * SEQ + qt * 64 + wm + gid + 8)) * NH + h) * DH;
#pragma unroll
        for (int nf = 0; nf < 8; nf++) {
            int cc = wdn + nf * 8 + 2 * tig;
            *(float2*)(g_attn + base0 + cc) = make_float2(o[nf][0] * li0, o[nf][1] * li0);
            *(float2*)(g_attn + base1 + cc) = make_float2(o[nf][2] * li1, o[nf][3] * li1);
        }
    }
}

// ---------------- launcher ---------------------------------------------------
extern "C" void kernel_launch(void* const* d_in, const int* in_sizes, int n_in,
                              void* d_out, int out_size) {
    const float* x  = (const float*)d_in[0];
    const float* Wq = (const float*)d_in[1];
    const float* Wk = (const float*)d_in[2];
    const float* Wv = (const float*)d_in[3];
    const float* Wo = (const float*)d_in[4];
    const float* Aq = (const float*)d_in[5];
    const float* Bq = (const float*)d_in[6];
    const float* Ak = (const float*)d_in[7];
    const float* Bk = (const float*)d_in[8];
    const float* Av = (const float*)d_in[9];
    const float* Bv = (const float*)d_in[10];
    const float* Ao = (const float*)d_in[11];
    const float* Bo = (const float*)d_in[12];
    float* out = (float*)d_out;

    float *q_ptr, *k_ptr, *v_ptr, *attn_ptr, *t_ptr;
    cudaGetSymbolAddress((void**)&q_ptr, g_q);
    cudaGetSymbolAddress((void**)&k_ptr, g_k);
    cudaGetSymbolAddress((void**)&v_ptr, g_v);
    cudaGetSymbolAddress((void**)&attn_ptr, g_attn);
    cudaGetSymbolAddress((void**)&t_ptr, g_t);

    cudaFuncSetAttribute(attn_mma_kernel,
                         cudaFuncAttributeMaxDynamicSharedMemorySize, ATTN_SMEM);

    rope_tables_kernel<<<(SEQ*(DH/2) + 255)/256, 256>>>();

    // Q
    lora_a_kernel<<<BB*SEQ/4, 256>>>(x, Aq, t_ptr, HIDDEN);
    gemm_lora_tf32<<<dim3(QDIM/BN, SEQ/BM, BB), 256>>>(x, Wq, t_ptr, Bq, q_ptr, QDIM, HIDDEN);

    // K
    lora_a_kernel<<<BB*SEQ/4, 256>>>(x, Ak, t_ptr, HIDDEN);
    gemm_lora_tf32<<<dim3(KVDIM/BN, SEQ/BM, BB), 256>>>(x, Wk, t_ptr, Bk, k_ptr, KVDIM, HIDDEN);

    // V
    lora_a_kernel<<<BB*SEQ/4, 256>>>(x, Av, t_ptr, HIDDEN);
    gemm_lora_tf32<<<dim3(KVDIM/BN, SEQ/BM, BB), 256>>>(x, Wv, t_ptr, Bv, v_ptr, KVDIM, HIDDEN);

    // RoPE
    {
        int tq = BB*SEQ*NH*(DH/2);
        rope_kernel<<<(tq + 255)/256, 256>>>(q_ptr, NH);
        int tk = BB*SEQ*NKV*(DH/2);
        rope_kernel<<<(tk + 255)/256, 256>>>(k_ptr, NKV);
    }

    // Attention (tensorized)
    attn_mma_kernel<<<dim3(SEQ/64, NH, BB), 256, ATTN_SMEM>>>();

    // Output projection
    lora_a_kernel<<<BB*SEQ/4, 256>>>(attn_ptr, Ao, t_ptr, QDIM);
    gemm_lora_tf32<<<dim3(HIDDEN/BN, SEQ/BM, BB), 256>>>(attn_ptr, Wo, t_ptr, Bo, out, HIDDEN, QDIM);
}

// round 4
// speedup vs baseline: 3.4537x; 1.1702x over previous
#include <cuda_runtime.h>
#include <math.h>
#include <stdint.h>

#define BB 4
#define SEQ 1024
#define HIDDEN 4096
#define NH 32
#define NKV 8
#define DH 128
#define RL 16
#define QDIM (NH*DH)     // 4096
#define KVDIM (NKV*DH)   // 1024

// ---------------- scratch (device globals; no allocations allowed) ----------
__device__ float g_q[(size_t)BB*SEQ*QDIM];
__device__ float g_k[(size_t)BB*SEQ*KVDIM];
__device__ float g_v[(size_t)BB*SEQ*KVDIM];
__device__ float g_attn[(size_t)BB*SEQ*QDIM];     // tf32-rounded bits (fp32)
__device__ float g_t[(size_t)3*BB*SEQ*RL];
__device__ float g_cos[SEQ*(DH/2)];
__device__ float g_sin[SEQ*(DH/2)];
// pre-rounded tf32 operands
__device__ uint32_t g_xt[(size_t)BB*SEQ*HIDDEN];
__device__ uint32_t g_wqt[(size_t)QDIM*HIDDEN];
__device__ uint32_t g_wkt[(size_t)KVDIM*HIDDEN];
__device__ uint32_t g_wvt[(size_t)KVDIM*HIDDEN];
__device__ uint32_t g_wot[(size_t)HIDDEN*QDIM];

// ---------------- helpers ----------------------------------------------------
__device__ __forceinline__ uint32_t f2tf(float x) {
    uint32_t r;
    asm("cvt.rna.tf32.f32 %0, %1;" : "=r"(r) : "f"(x));
    return r;
}

#define MMA_TF32(c0,c1,c2,c3,a0,a1,a2,a3,b0,b1)                              \
    asm volatile("mma.sync.aligned.m16n8k8.row.col.f32.tf32.tf32.f32 "       \
        "{%0,%1,%2,%3}, {%4,%5,%6,%7}, {%8,%9}, {%0,%1,%2,%3};"              \
        : "+f"(c0),"+f"(c1),"+f"(c2),"+f"(c3)                                \
        : "r"(a0),"r"(a1),"r"(a2),"r"(a3),"r"(b0),"r"(b1))

__device__ __forceinline__ void cp_async16(void* smem_dst, const void* gsrc) {
    uint32_t d = (uint32_t)__cvta_generic_to_shared(smem_dst);
    asm volatile("cp.async.cg.shared.global [%0], [%1], 16;" :: "r"(d), "l"(gsrc));
}
__device__ __forceinline__ void cp_commit() {
    asm volatile("cp.async.commit_group;");
}

// ---------------- tf32 pre-round convert -------------------------------------
__global__ void cvt_tf32_kernel(const float4* __restrict__ in,
                                uint4* __restrict__ out, int n4) {
    int i = blockIdx.x * blockDim.x + threadIdx.x;
    if (i >= n4) return;
    float4 v = in[i];
    uint4 o;
    o.x = f2tf(v.x); o.y = f2tf(v.y); o.z = f2tf(v.z); o.w = f2tf(v.w);
    out[i] = o;
}

// ---------------- RoPE tables ----------------------------------------------
__global__ void rope_tables_kernel() {
    int idx = blockIdx.x * blockDim.x + threadIdx.x;
    if (idx >= SEQ * (DH/2)) return;
    int s = idx / (DH/2);
    int j = idx % (DH/2);
    float e = -(float)j * (13.287712379549449f / 64.0f);
    float inv = exp2f(e);
    float ang = (float)s * inv;
    g_cos[idx] = cosf(ang);
    g_sin[idx] = sinf(ang);
}

// ---------------- fused LoRA A-side for Q/K/V --------------------------------
__global__ __launch_bounds__(256) void lora_qkv_kernel(
    const float* __restrict__ x, const float* __restrict__ Aq,
    const float* __restrict__ Ak, const float* __restrict__ Av,
    float* __restrict__ t)
{
    const int g = threadIdx.x >> 6;
    const int j = threadIdx.x & 63;
    const int row = blockIdx.x * 4 + g;
    const int b = row / SEQ;
    const float* xr = x + (size_t)row * HIDDEN;
    const float* Ab0 = Aq + (size_t)b * RL * HIDDEN;
    const float* Ab1 = Ak + (size_t)b * RL * HIDDEN;
    const float* Ab2 = Av + (size_t)b * RL * HIDDEN;

    float acc[3][RL];
#pragma unroll
    for (int p = 0; p < 3; p++)
#pragma unroll
        for (int r = 0; r < RL; r++) acc[p][r] = 0.f;

    for (int k = j * 4; k < HIDDEN; k += 256) {
        float4 xv = *(const float4*)(xr + k);
#pragma unroll
        for (int r = 0; r < RL; r++) {
            float4 a0 = *(const float4*)(Ab0 + (size_t)r * HIDDEN + k);
            float4 a1 = *(const float4*)(Ab1 + (size_t)r * HIDDEN + k);
            float4 a2 = *(const float4*)(Ab2 + (size_t)r * HIDDEN + k);
            acc[0][r] += fmaf(xv.x, a0.x, fmaf(xv.y, a0.y, fmaf(xv.z, a0.z, xv.w * a0.w)));
            acc[1][r] += fmaf(xv.x, a1.x, fmaf(xv.y, a1.y, fmaf(xv.z, a1.z, xv.w * a1.w)));
            acc[2][r] += fmaf(xv.x, a2.x, fmaf(xv.y, a2.y, fmaf(xv.z, a2.z, xv.w * a2.w)));
        }
    }

    __shared__ float red[4][64][17];
#pragma unroll
    for (int p = 0; p < 3; p++) {
        __syncthreads();
#pragma unroll
        for (int r = 0; r < RL; r++) red[g][j][r] = acc[p][r];
        __syncthreads();
        if (j < RL) {
            float s = 0.f;
#pragma unroll 8
            for (int jj = 0; jj < 64; jj++) s += red[g][jj][j];
            t[(size_t)p * BB * SEQ * RL + (size_t)row * RL + j] = s;
        }
    }
}

// ---------------- LoRA A-side (single, for O path) ---------------------------
__global__ __launch_bounds__(256) void lora_a_kernel(
    const float* __restrict__ x, const float* __restrict__ A,
    float* __restrict__ t, int K)
{
    const int g = threadIdx.x >> 6;
    const int j = threadIdx.x & 63;
    const int row = blockIdx.x * 4 + g;
    const int b = row / SEQ;
    const float* xr = x + (size_t)row * K;
    const float* Ab = A + (size_t)b * RL * K;

    float acc[RL];
#pragma unroll
    for (int r = 0; r < RL; r++) acc[r] = 0.f;

    for (int k = j * 4; k < K; k += 256) {
        float4 xv = *(const float4*)(xr + k);
#pragma unroll
        for (int r = 0; r < RL; r++) {
            float4 av = *(const float4*)(Ab + (size_t)r * K + k);
            acc[r] += fmaf(xv.x, av.x, fmaf(xv.y, av.y, fmaf(xv.z, av.z, xv.w * av.w)));
        }
    }

    __shared__ float red[4][64][17];
#pragma unroll
    for (int r = 0; r < RL; r++) red[g][j][r] = acc[r];
    __syncthreads();
    if (j < RL) {
        float s = 0.f;
#pragma unroll 8
        for (int jj = 0; jj < 64; jj++) s += red[g][jj][j];
        t[(size_t)row * RL + j] = s;
    }
}

// ---------------- tf32 MMA GEMM v3: cp.async double-buffered -----------------
// C[b] (SEQ x N) = Xt[b] (SEQ x K, tf32 bits) @ Wt^T + T[b] @ BL[b]^T
#define BM 128
#define BN 128
#define BK 32
#define KPAD 36
#define GEMM_SMEM (4*128*KPAD*4)   // 2 stages x (A+B) x 128x36 u32 = 73728 B

__global__ __launch_bounds__(256, 2) void gemm_lora_v3(
    const uint32_t* __restrict__ Xt, const uint32_t* __restrict__ Wt,
    const float* __restrict__ T, const float* __restrict__ BL,
    float* __restrict__ C, int N, int K)
{
    extern __shared__ uint32_t sm3[];
    uint32_t* AsB = sm3;                    // [2][128][36]
    uint32_t* BsB = sm3 + 2 * 128 * KPAD;   // [2][128][36]

    const int b  = blockIdx.z;
    const int n0 = blockIdx.x * BN;
    const int m0 = blockIdx.y * BM;
    const uint32_t* Xb = Xt + (size_t)b * SEQ * K;
    const float* Tb = T + (size_t)b * SEQ * RL;
    const float* Ub = BL + (size_t)b * N * RL;
    float* Cb = C + (size_t)b * SEQ * N;

    const int tid  = threadIdx.x;
    const int warp = tid >> 5;
    const int lane = tid & 31;
    const int wm = (warp & 3) * 32;
    const int wn = (warp >> 2) * 64;
    const int gid = lane >> 2;
    const int tig = lane & 3;

    float acc[2][8][4];
#pragma unroll
    for (int mf = 0; mf < 2; mf++)
#pragma unroll
        for (int nf = 0; nf < 8; nf++)
#pragma unroll
            for (int c = 0; c < 4; c++) acc[mf][nf][c] = 0.f;

    const int KT = K / BK;

    // prologue: stage 0
    {
#pragma unroll
        for (int i = 0; i < 4; i++) {
            int idx = tid + i * 256;
            int row = idx >> 3, seg = idx & 7;
            cp_async16(&AsB[row * KPAD + seg * 4], Xb + (size_t)(m0 + row) * K + seg * 4);
            cp_async16(&BsB[row * KPAD + seg * 4], Wt + (size_t)(n0 + row) * K + seg * 4);
        }
        cp_commit();
    }

    for (int kt = 0; kt < KT; kt++) {
        const int s = kt & 1;
        if (kt + 1 < KT) {
            const int sn = s ^ 1;
            const int k0 = (kt + 1) * BK;
#pragma unroll
            for (int i = 0; i < 4; i++) {
                int idx = tid + i * 256;
                int row = idx >> 3, seg = idx & 7;
                cp_async16(&AsB[sn * 128 * KPAD + row * KPAD + seg * 4],
                           Xb + (size_t)(m0 + row) * K + k0 + seg * 4);
                cp_async16(&BsB[sn * 128 * KPAD + row * KPAD + seg * 4],
                           Wt + (size_t)(n0 + row) * K + k0 + seg * 4);
            }
            cp_commit();
            asm volatile("cp.async.wait_group 1;");
        } else {
            asm volatile("cp.async.wait_group 0;");
        }
        __syncthreads();

        const uint32_t* As = AsB + s * 128 * KPAD;
        const uint32_t* Bs = BsB + s * 128 * KPAD;
#pragma unroll
        for (int ks = 0; ks < 4; ks++) {
            const int kb = ks * 8;
            uint32_t a[2][4];
#pragma unroll
            for (int mf = 0; mf < 2; mf++) {
                int mrow = wm + mf * 16 + gid;
                a[mf][0] = As[mrow * KPAD + kb + tig];
                a[mf][1] = As[(mrow + 8) * KPAD + kb + tig];
                a[mf][2] = As[mrow * KPAD + kb + tig + 4];
                a[mf][3] = As[(mrow + 8) * KPAD + kb + tig + 4];
            }
#pragma unroll
            for (int nf = 0; nf < 8; nf++) {
                int nrow = wn + nf * 8 + gid;
                uint32_t b0 = Bs[nrow * KPAD + kb + tig];
                uint32_t b1 = Bs[nrow * KPAD + kb + tig + 4];
                MMA_TF32(acc[0][nf][0], acc[0][nf][1], acc[0][nf][2], acc[0][nf][3],
                         a[0][0], a[0][1], a[0][2], a[0][3], b0, b1);
                MMA_TF32(acc[1][nf][0], acc[1][nf][1], acc[1][nf][2], acc[1][nf][3],
                         a[1][0], a[1][1], a[1][2], a[1][3], b0, b1);
            }
        }
        __syncthreads();   // protect stage being overwritten next iter
    }

    // ---- LoRA-B epilogue (fp32 exact), reuse smem ----
    float* Ts = (float*)sm3;            // [128][16]
    float* Us = (float*)(sm3 + 128 * RL);
#pragma unroll
    for (int i = 0; i < 2; i++) {
        int f4 = tid + i * 256;
        int row = f4 >> 2;
        int c4 = (f4 & 3) * 4;
        *(float4*)&Ts[row * RL + c4] = *(const float4*)&Tb[(size_t)(m0 + row) * RL + c4];
        *(float4*)&Us[row * RL + c4] = *(const float4*)&Ub[(size_t)(n0 + row) * RL + c4];
    }
    __syncthreads();

#pragma unroll
    for (int mf = 0; mf < 2; mf++) {
#pragma unroll
        for (int rr = 0; rr < 2; rr++) {
            int m_local = wm + mf * 16 + rr * 8 + gid;
            float tv[RL];
#pragma unroll
            for (int r = 0; r < RL; r++) tv[r] = Ts[m_local * RL + r];
            size_t crow = (size_t)(m0 + m_local) * N + n0;
#pragma unroll
            for (int nf = 0; nf < 8; nf++) {
                int n_local = wn + nf * 8 + 2 * tig;
                float s0 = acc[mf][nf][rr * 2 + 0];
                float s1 = acc[mf][nf][rr * 2 + 1];
#pragma unroll
                for (int r = 0; r < RL; r++) {
                    s0 = fmaf(tv[r], Us[n_local * RL + r], s0);
                    s1 = fmaf(tv[r], Us[(n_local + 1) * RL + r], s1);
                }
                *(float2*)&Cb[crow + n_local] = make_float2(s0, s1);
            }
        }
    }
}

// ---------------- RoPE in-place ---------------------------------------------
__global__ void rope_kernel(float* __restrict__ p, int nheads) {
    int idx = blockIdx.x * blockDim.x + threadIdx.x;
    int total = BB * SEQ * nheads * (DH/2);
    if (idx >= total) return;
    int j = idx & 63;
    int h = (idx >> 6) % nheads;
    int s = (idx / (64 * nheads)) % SEQ;
    int b = idx / (64 * nheads * SEQ);
    size_t base = (((size_t)(b * SEQ + s)) * nheads + h) * DH;
    float c  = g_cos[s * 64 + j];
    float sn = g_sin[s * 64 + j];
    float x1 = p[base + j];
    float x2 = p[base + j + 64];
    p[base + j]      = fmaf(x1, c, -x2 * sn);
    p[base + j + 64] = fmaf(x2, c,  x1 * sn);
}

// ---------------- Flash attention (split-tf32 MMA, causal, GQA) --------------
#define ATTN_SMEM 155392
#define QKS 132
#define VSS 68
#define PSS 68
#define SWC(d) ((d) + ((d) >> 5))

__global__ __launch_bounds__(256, 1) void attn_mma_kernel() {
    extern __shared__ char smraw[];
    uint32_t* Qhi = (uint32_t*)(smraw);
    uint32_t* Qlo = (uint32_t*)(smraw + 33792);
    uint32_t* Khi = (uint32_t*)(smraw + 67584);
    uint32_t* Klo = (uint32_t*)(smraw + 67584 + 34816);
    uint32_t* Vhi = Khi;
    uint32_t* Vlo = Klo;
    float*    Psf = (float*)(smraw + 137216);
    uint32_t* Psu = (uint32_t*)Psf;
    float* mrow = (float*)(smraw + 154624);
    float* lrow = mrow + 64;
    float* arow = mrow + 128;

    const int qt = (SEQ/64 - 1) - blockIdx.x;
    const int h  = blockIdx.y;
    const int b  = blockIdx.z;
    const int hk = h >> 2;
    const int tid  = threadIdx.x;
    const int warp = tid >> 5;
    const int lane = tid & 31;
    const int gid = lane >> 2;
    const int tig = lane & 3;
    const int wm  = (warp & 3) * 16;
    const int wn  = (warp >> 2) * 32;
    const int wdn = (warp >> 2) * 64;

    const float scale = 0.08838834764831845f;

    {
        int r = tid >> 2;
        int dbase = (tid & 3) * 32;
        const float* src = g_q + (((size_t)(b * SEQ + qt * 64 + r)) * NH + h) * DH + dbase;
#pragma unroll
        for (int u = 0; u < 8; u++) {
            float4 v4 = *(const float4*)(src + u * 4);
            v4.x *= scale; v4.y *= scale; v4.z *= scale; v4.w *= scale;
            int d = dbase + u * 4;
            int cb = r * QKS + SWC(d);
            uint32_t h0 = f2tf(v4.x), h1 = f2tf(v4.y), h2 = f2tf(v4.z), h3 = f2tf(v4.w);
            Qhi[cb+0] = h0; Qhi[cb+1] = h1; Qhi[cb+2] = h2; Qhi[cb+3] = h3;
            Qlo[cb+0] = f2tf(v4.x - __uint_as_float(h0));
            Qlo[cb+1] = f2tf(v4.y - __uint_as_float(h1));
            Qlo[cb+2] = f2tf(v4.z - __uint_as_float(h2));
            Qlo[cb+3] = f2tf(v4.w - __uint_as_float(h3));
        }
    }
    if (tid < 64) { mrow[tid] = -1e30f; lrow[tid] = 0.f; }
    __syncthreads();

    uint32_t ah[16][4];
#pragma unroll
    for (int ks = 0; ks < 16; ks++) {
        int kb = ks * 8;
        int c = kb + (kb >> 5) + tig;
        ah[ks][0] = Qhi[(wm + gid)     * QKS + c];
        ah[ks][1] = Qhi[(wm + gid + 8) * QKS + c];
        ah[ks][2] = Qhi[(wm + gid)     * QKS + c + 4];
        ah[ks][3] = Qhi[(wm + gid + 8) * QKS + c + 4];
    }

    float o[8][4];
#pragma unroll
    for (int nf = 0; nf < 8; nf++)
#pragma unroll
        for (int c = 0; c < 4; c++) o[nf][c] = 0.f;

    for (int jt = 0; jt <= qt; jt++) {
        __syncthreads();

        {
            int r = tid >> 2;
            int dbase = (tid & 3) * 32;
            const float* src = g_k + (((size_t)(b * SEQ + jt * 64 + r)) * NKV + hk) * DH + dbase;
#pragma unroll
            for (int u = 0; u < 8; u++) {
                float4 v4 = *(const float4*)(src + u * 4);
                int d = dbase + u * 4;
                int cb = r * QKS + SWC(d);
                uint32_t h0 = f2tf(v4.x), h1 = f2tf(v4.y), h2 = f2tf(v4.z), h3 = f2tf(v4.w);
                Khi[cb+0] = h0; Khi[cb+1] = h1; Khi[cb+2] = h2; Khi[cb+3] = h3;
                Klo[cb+0] = f2tf(v4.x - __uint_as_float(h0));
                Klo[cb+1] = f2tf(v4.y - __uint_as_float(h1));
                Klo[cb+2] = f2tf(v4.z - __uint_as_float(h2));
                Klo[cb+3] = f2tf(v4.w - __uint_as_float(h3));
            }
        }
        __syncthreads();

        float s[4][4];
#pragma unroll
        for (int nf = 0; nf < 4; nf++)
#pragma unroll
            for (int c = 0; c < 4; c++) s[nf][c] = 0.f;

#pragma unroll
        for (int ks = 0; ks < 16; ks++) {
            int kb = ks * 8;
            int c = kb + (kb >> 5) + tig;
            uint32_t al0 = Qlo[(wm + gid)     * QKS + c];
            uint32_t al1 = Qlo[(wm + gid + 8) * QKS + c];
            uint32_t al2 = Qlo[(wm + gid)     * QKS + c + 4];
            uint32_t al3 = Qlo[(wm + gid + 8) * QKS + c + 4];
#pragma unroll
            for (int nf = 0; nf < 4; nf++) {
                int nr = (wn + nf * 8 + gid) * QKS;
                uint32_t bh0 = Khi[nr + c];
                uint32_t bh1 = Khi[nr + c + 4];
                uint32_t bl0 = Klo[nr + c];
                uint32_t bl1 = Klo[nr + c + 4];
                MMA_TF32(s[nf][0], s[nf][1], s[nf][2], s[nf][3],
                         ah[ks][0], ah[ks][1], ah[ks][2], ah[ks][3], bh0, bh1);
                MMA_TF32(s[nf][0], s[nf][1], s[nf][2], s[nf][3],
                         al0, al1, al2, al3, bh0, bh1);
                MMA_TF32(s[nf][0], s[nf][1], s[nf][2], s[nf][3],
                         ah[ks][0], ah[ks][1], ah[ks][2], ah[ks][3], bl0, bl1);
            }
        }

        {
            int row0 = wm + gid, row1 = row0 + 8;
            int rg0 = qt * 64 + row0, rg1 = qt * 64 + row1;
#pragma unroll
            for (int nf = 0; nf < 4; nf++) {
                int cc = wn + nf * 8 + 2 * tig;
                int cg = jt * 64 + cc;
                float2 w0, w1;
                w0.x = (cg     <= rg0) ? s[nf][0] : -1e30f;
                w0.y = (cg + 1 <= rg0) ? s[nf][1] : -1e30f;
                w1.x = (cg     <= rg1) ? s[nf][2] : -1e30f;
                w1.y = (cg + 1 <= rg1) ? s[nf][3] : -1e30f;
                *(float2*)(Psf + row0 * PSS + cc) = w0;
                *(float2*)(Psf + row1 * PSS + cc) = w1;
            }
        }
        __syncthreads();

        int vj = tid & 63;
        int vdc = (tid >> 6) * 32;
        const float* vsrc = g_v + (((size_t)(b * SEQ + jt * 64 + vj)) * NKV + hk) * DH + vdc;
        float4 vv[8];
#pragma unroll
        for (int u = 0; u < 8; u++) vv[u] = *(const float4*)(vsrc + u * 4);

        {
            int sr = tid >> 2;
            int sc = (tid & 3) * 16;
            float* prow = Psf + sr * PSS + sc;
            float pv[16];
            float mx = -1e30f;
#pragma unroll
            for (int i = 0; i < 16; i++) { pv[i] = prow[i]; mx = fmaxf(mx, pv[i]); }
            mx = fmaxf(mx, __shfl_xor_sync(0xffffffffu, mx, 1));
            mx = fmaxf(mx, __shfl_xor_sync(0xffffffffu, mx, 2));
            float mo = mrow[sr];
            mx = fmaxf(mx, mo);
            float sum = 0.f;
            uint32_t* purow = Psu + sr * PSS + sc;
#pragma unroll
            for (int i = 0; i < 16; i++) {
                float e = __expf(pv[i] - mx);
                sum += e;
                purow[i] = f2tf(e);
            }
            sum += __shfl_xor_sync(0xffffffffu, sum, 1);
            sum += __shfl_xor_sync(0xffffffffu, sum, 2);
            if ((tid & 3) == 0) {
                float alp = __expf(mo - mx);
                lrow[sr] = lrow[sr] * alp + sum;
                mrow[sr] = mx;
                arow[sr] = alp;
            }
        }

#pragma unroll
        for (int u = 0; u < 8; u++) {
            int d0 = vdc + u * 4;
            float x0 = vv[u].x, x1 = vv[u].y, x2 = vv[u].z, x3 = vv[u].w;
            uint32_t h0 = f2tf(x0), h1 = f2tf(x1), h2 = f2tf(x2), h3 = f2tf(x3);
            Vhi[(d0+0) * VSS + vj] = h0;
            Vhi[(d0+1) * VSS + vj] = h1;
            Vhi[(d0+2) * VSS + vj] = h2;
            Vhi[(d0+3) * VSS + vj] = h3;
            Vlo[(d0+0) * VSS + vj] = f2tf(x0 - __uint_as_float(h0));
            Vlo[(d0+1) * VSS + vj] = f2tf(x1 - __uint_as_float(h1));
            Vlo[(d0+2) * VSS + vj] = f2tf(x2 - __uint_as_float(h2));
            Vlo[(d0+3) * VSS + vj] = f2tf(x3 - __uint_as_float(h3));
        }
        __syncthreads();

        {
            float a0 = arow[wm + gid];
            float a1 = arow[wm + gid + 8];
#pragma unroll
            for (int nf = 0; nf < 8; nf++) {
                o[nf][0] *= a0; o[nf][1] *= a0;
                o[nf][2] *= a1; o[nf][3] *= a1;
            }
        }

#pragma unroll
        for (int ks = 0; ks < 8; ks++) {
            int kb = ks * 8;
            uint32_t pa0 = Psu[(wm + gid)     * PSS + kb + tig];
            uint32_t pa1 = Psu[(wm + gid + 8) * PSS + kb + tig];
            uint32_t pa2 = Psu[(wm + gid)     * PSS + kb + tig + 4];
            uint32_t pa3 = Psu[(wm + gid + 8) * PSS + kb + tig + 4];
#pragma unroll
            for (int nf = 0; nf < 8; nf++) {
                int dv = (wdn + nf * 8 + gid) * VSS + kb + tig;
                uint32_t bh0 = Vhi[dv], bh1 = Vhi[dv + 4];
                uint32_t bl0 = Vlo[dv], bl1 = Vlo[dv + 4];
                MMA_TF32(o[nf][0], o[nf][1], o[nf][2], o[nf][3],
                         pa0, pa1, pa2, pa3, bh0, bh1);
                MMA_TF32(o[nf][0], o[nf][1], o[nf][2], o[nf][3],
                         pa0, pa1, pa2, pa3, bl0, bl1);
            }
        }
    }

    // epilogue: normalize, pre-round to tf32 bits (feeds O-GEMM directly)
    {
        float li0 = 1.f / lrow[wm + gid];
        float li1 = 1.f / lrow[wm + gid + 8];
        size_t base0 = (((size_t)(b * SEQ + qt * 64 + wm + gid))     * NH + h) * DH;
        size_t base1 = (((size_t)(b * SEQ + qt * 64 + wm + gid + 8)) * NH + h) * DH;
#pragma unroll
        for (int nf = 0; nf < 8; nf++) {
            int cc = wdn + nf * 8 + 2 * tig;
            float2 w0 = make_float2(__uint_as_float(f2tf(o[nf][0] * li0)),
                                    __uint_as_float(f2tf(o[nf][1] * li0)));
            float2 w1 = make_float2(__uint_as_float(f2tf(o[nf][2] * li1)),
                                    __uint_as_float(f2tf(o[nf][3] * li1)));
            *(float2*)(g_attn + base0 + cc) = w0;
            *(float2*)(g_attn + base1 + cc) = w1;
        }
    }
}

// ---------------- launcher ---------------------------------------------------
extern "C" void kernel_launch(void* const* d_in, const int* in_sizes, int n_in,
                              void* d_out, int out_size) {
    const float* x  = (const float*)d_in[0];
    const float* Wq = (const float*)d_in[1];
    const float* Wk = (const float*)d_in[2];
    const float* Wv = (const float*)d_in[3];
    const float* Wo = (const float*)d_in[4];
    const float* Aq = (const float*)d_in[5];
    const float* Bq = (const float*)d_in[6];
    const float* Ak = (const float*)d_in[7];
    const float* Bk = (const float*)d_in[8];
    const float* Av = (const float*)d_in[9];
    const float* Bv = (const float*)d_in[10];
    const float* Ao = (const float*)d_in[11];
    const float* Bo = (const float*)d_in[12];
    float* out = (float*)d_out;

    float *q_ptr, *k_ptr, *v_ptr, *attn_ptr, *t_ptr;
    uint32_t *xt_ptr, *wqt_ptr, *wkt_ptr, *wvt_ptr, *wot_ptr;
    cudaGetSymbolAddress((void**)&q_ptr, g_q);
    cudaGetSymbolAddress((void**)&k_ptr, g_k);
    cudaGetSymbolAddress((void**)&v_ptr, g_v);
    cudaGetSymbolAddress((void**)&attn_ptr, g_attn);
    cudaGetSymbolAddress((void**)&t_ptr, g_t);
    cudaGetSymbolAddress((void**)&xt_ptr, g_xt);
    cudaGetSymbolAddress((void**)&wqt_ptr, g_wqt);
    cudaGetSymbolAddress((void**)&wkt_ptr, g_wkt);
    cudaGetSymbolAddress((void**)&wvt_ptr, g_wvt);
    cudaGetSymbolAddress((void**)&wot_ptr, g_wot);

    cudaFuncSetAttribute(attn_mma_kernel,
                         cudaFuncAttributeMaxDynamicSharedMemorySize, ATTN_SMEM);
    cudaFuncSetAttribute(gemm_lora_v3,
                         cudaFuncAttributeMaxDynamicSharedMemorySize, GEMM_SMEM);

    rope_tables_kernel<<<(SEQ*(DH/2) + 255)/256, 256>>>();

    // pre-round operands to tf32-RN
    {
        int n4;
        n4 = BB*SEQ*HIDDEN/4;
        cvt_tf32_kernel<<<(n4 + 255)/256, 256>>>((const float4*)x, (uint4*)xt_ptr, n4);
        n4 = QDIM*HIDDEN/4;
        cvt_tf32_kernel<<<(n4 + 255)/256, 256>>>((const float4*)Wq, (uint4*)wqt_ptr, n4);
        n4 = KVDIM*HIDDEN/4;
        cvt_tf32_kernel<<<(n4 + 255)/256, 256>>>((const float4*)Wk, (uint4*)wkt_ptr, n4);
        cvt_tf32_kernel<<<(n4 + 255)/256, 256>>>((const float4*)Wv, (uint4*)wvt_ptr, n4);
        n4 = HIDDEN*QDIM/4;
        cvt_tf32_kernel<<<(n4 + 255)/256, 256>>>((const float4*)Wo, (uint4*)wot_ptr, n4);
    }

    // fused LoRA-A for q/k/v
    lora_qkv_kernel<<<BB*SEQ/4, 256>>>(x, Aq, Ak, Av, t_ptr);

    const size_t TS = (size_t)BB*SEQ*RL;
    gemm_lora_v3<<<dim3(QDIM/BN, SEQ/BM, BB), 256, GEMM_SMEM>>>(
        xt_ptr, wqt_ptr, t_ptr,          Bq, q_ptr, QDIM, HIDDEN);
    gemm_lora_v3<<<dim3(KVDIM/BN, SEQ/BM, BB), 256, GEMM_SMEM>>>(
        xt_ptr, wkt_ptr, t_ptr + TS,     Bk, k_ptr, KVDIM, HIDDEN);
    gemm_lora_v3<<<dim3(KVDIM/BN, SEQ/BM, BB), 256, GEMM_SMEM>>>(
        xt_ptr, wvt_ptr, t_ptr + 2*TS,   Bv, v_ptr, KVDIM, HIDDEN);

    {
        int tq = BB*SEQ*NH*(DH/2);
        rope_kernel<<<(tq + 255)/256, 256>>>(q_ptr, NH);
        int tk = BB*SEQ*NKV*(DH/2);
        rope_kernel<<<(tk + 255)/256, 256>>>(k_ptr, NKV);
    }

    attn_mma_kernel<<<dim3(SEQ/64, NH, BB), 256, ATTN_SMEM>>>();

    lora_a_kernel<<<BB*SEQ/4, 256>>>(attn_ptr, Ao, t_ptr, QDIM);
    gemm_lora_v3<<<dim3(HIDDEN/BN, SEQ/BM, BB), 256, GEMM_SMEM>>>(
        (const uint32_t*)attn_ptr, wot_ptr, t_ptr, Bo, out, HIDDEN, QDIM);
}